// round 2
// baseline (speedup 1.0000x reference)
#include <cuda_runtime.h>

#define VOCAB 32000
#define EDIM  1024
#define HDIM  1024
#define NLAY  2
#define BSZ   64
#define TST   64
#define GDIM  4096          // 4*HDIM
#define KS_L  8             // split-K chunks for LSTM GEMMs (chunk = 128)
#define KS_E  8             // split-K chunks for o2emb GEMM (chunk = 128)
#define NB_V  (VOCAB/128)   // 250 score blocks
#define START_TOK 1

// ---------------- scratch (device globals; no allocation allowed) ----------
__device__ float g_h[NLAY][BSZ][HDIM];
__device__ float g_c[NLAY][BSZ][HDIM];
__device__ float g_gates[KS_L][BSZ][GDIM];
__device__ float g_hidp[KS_E][BSZ][EDIM];
__device__ float g_hid[BSZ][EDIM];
__device__ float g_pval[BSZ][NB_V];
__device__ int   g_pidx[BSZ][NB_V];
__device__ int   g_tok[BSZ];

// ---------------- GEMM tile helpers (BM=64, BN=128, BK=32, 128 thr, 8x8) ---
// As stored transposed [k][b] (stride 68), Bs transposed [k][n] (stride 132)
// so the inner product reads are conflict-free float4 LDS.

__device__ __forceinline__ void load_A(float As[32][68], const float* __restrict__ A,
                                       int lda, int kpos) {
  const int tid = threadIdx.x;
#pragma unroll
  for (int p = 0; p < 4; p++) {
    int idx = p * 128 + tid;
    int r = idx >> 3, c4 = idx & 7;
    float4 v = *(const float4*)(A + (size_t)r * lda + kpos + c4 * 4);
    As[c4 * 4 + 0][r] = v.x; As[c4 * 4 + 1][r] = v.y;
    As[c4 * 4 + 2][r] = v.z; As[c4 * 4 + 3][r] = v.w;
  }
}

__device__ __forceinline__ void load_A_gather(float As[32][68], const float* __restrict__ A,
                                              int lda, int kpos, const int* stok) {
  const int tid = threadIdx.x;
#pragma unroll
  for (int p = 0; p < 4; p++) {
    int idx = p * 128 + tid;
    int r = idx >> 3, c4 = idx & 7;
    int row = stok[r];
    float4 v = *(const float4*)(A + (size_t)row * lda + kpos + c4 * 4);
    As[c4 * 4 + 0][r] = v.x; As[c4 * 4 + 1][r] = v.y;
    As[c4 * 4 + 2][r] = v.z; As[c4 * 4 + 3][r] = v.w;
  }
}

__device__ __forceinline__ void load_B(float Bs[32][132], const float* __restrict__ W,
                                       int ldw, int n0, int kpos) {
  const int tid = threadIdx.x;
#pragma unroll
  for (int p = 0; p < 8; p++) {
    int idx = p * 128 + tid;
    int r = idx >> 3, c4 = idx & 7;
    float4 v = *(const float4*)(W + (size_t)(n0 + r) * ldw + kpos + c4 * 4);
    Bs[c4 * 4 + 0][r] = v.x; Bs[c4 * 4 + 1][r] = v.y;
    Bs[c4 * 4 + 2][r] = v.z; Bs[c4 * 4 + 3][r] = v.w;
  }
}

__device__ __forceinline__ void mma32(const float As[32][68], const float Bs[32][132],
                                      float acc[8][8], int ty, int tx) {
#pragma unroll
  for (int k = 0; k < 32; k++) {
    float a[8], b[8];
    *(float4*)(a)     = *(const float4*)(&As[k][ty * 8]);
    *(float4*)(a + 4) = *(const float4*)(&As[k][ty * 8 + 4]);
    *(float4*)(b)     = *(const float4*)(&Bs[k][tx * 8]);
    *(float4*)(b + 4) = *(const float4*)(&Bs[k][tx * 8 + 4]);
#pragma unroll
    for (int i = 0; i < 8; i++)
#pragma unroll
      for (int j = 0; j < 8; j++)
        acc[i][j] = fmaf(a[i], b[j], acc[i][j]);
  }
}

// ---------------- kernels ----------------

__global__ void k_init() {
  int i = blockIdx.x * blockDim.x + threadIdx.x;
  if (i < NLAY * BSZ * HDIM) {
    (&g_h[0][0][0])[i] = 0.f;
    (&g_c[0][0][0])[i] = 0.f;
  }
  if (i < BSZ) g_tok[i] = START_TOK;
}

// gates partial: g_gates[chunk][b][n] = x@w_ih^T + h@w_hh^T over K-chunk
__global__ __launch_bounds__(128) void k_gates(const float* __restrict__ emb,
                                               const float* __restrict__ wih,
                                               const float* __restrict__ whh,
                                               int layer) {
  __shared__ float As[32][68];
  __shared__ float Bs[32][132];
  __shared__ int stok[BSZ];
  const int tid = threadIdx.x;
  if (layer == 0 && tid < BSZ) stok[tid] = g_tok[tid];
  __syncthreads();

  const int n0 = blockIdx.x * 128;
  const int kc = blockIdx.y * (HDIM / KS_L);
  const int ty = tid >> 4, tx = tid & 15;
  float acc[8][8];
#pragma unroll
  for (int i = 0; i < 8; i++)
#pragma unroll
    for (int j = 0; j < 8; j++) acc[i][j] = 0.f;

  const float* xsrc = (layer == 0) ? emb : &g_h[0][0][0];
  const float* hin  = &g_h[layer][0][0];

  for (int kt = 0; kt < HDIM / KS_L; kt += 32) {
    if (layer == 0) load_A_gather(As, emb, EDIM, kc + kt, stok);
    else            load_A(As, xsrc, HDIM, kc + kt);
    load_B(Bs, wih, HDIM, n0, kc + kt);
    __syncthreads();
    mma32(As, Bs, acc, ty, tx);
    __syncthreads();
  }
  for (int kt = 0; kt < HDIM / KS_L; kt += 32) {
    load_A(As, hin, HDIM, kc + kt);
    load_B(Bs, whh, HDIM, n0, kc + kt);
    __syncthreads();
    mma32(As, Bs, acc, ty, tx);
    __syncthreads();
  }

#pragma unroll
  for (int i = 0; i < 8; i++) {
    int b = ty * 8 + i;
    float* dst = &g_gates[blockIdx.y][b][n0 + tx * 8];
    *(float4*)(dst)     = make_float4(acc[i][0], acc[i][1], acc[i][2], acc[i][3]);
    *(float4*)(dst + 4) = make_float4(acc[i][4], acc[i][5], acc[i][6], acc[i][7]);
  }
}

// reduce split-K partials + biases, apply LSTM cell (gate order i,f,g,o)
__global__ void k_act(const float* __restrict__ bih, const float* __restrict__ bhh,
                      int layer) {
  int i = blockIdx.x * blockDim.x + threadIdx.x;
  if (i >= BSZ * HDIM) return;
  int b = i >> 10, hh = i & (HDIM - 1);
  float gi = bih[hh]            + bhh[hh];
  float gf = bih[HDIM + hh]     + bhh[HDIM + hh];
  float gg = bih[2 * HDIM + hh] + bhh[2 * HDIM + hh];
  float go = bih[3 * HDIM + hh] + bhh[3 * HDIM + hh];
#pragma unroll
  for (int c = 0; c < KS_L; c++) {
    gi += g_gates[c][b][hh];
    gf += g_gates[c][b][HDIM + hh];
    gg += g_gates[c][b][2 * HDIM + hh];
    go += g_gates[c][b][3 * HDIM + hh];
  }
  float si = 1.f / (1.f + expf(-gi));
  float sf = 1.f / (1.f + expf(-gf));
  float so = 1.f / (1.f + expf(-go));
  float tg = tanhf(gg);
  float cn = sf * g_c[layer][b][hh] + si * tg;
  float hn = so * tanhf(cn);
  g_c[layer][b][hh] = cn;
  g_h[layer][b][hh] = hn;
}

// o2emb partial GEMM: g_hidp[chunk][b][e] = h_top @ o2emb_w^T over K-chunk
__global__ __launch_bounds__(128) void k_o2emb(const float* __restrict__ w) {
  __shared__ float As[32][68];
  __shared__ float Bs[32][132];
  const int tid = threadIdx.x;
  const int n0 = blockIdx.x * 128;
  const int kc = blockIdx.y * (HDIM / KS_E);
  const int ty = tid >> 4, tx = tid & 15;
  float acc[8][8];
#pragma unroll
  for (int i = 0; i < 8; i++)
#pragma unroll
    for (int j = 0; j < 8; j++) acc[i][j] = 0.f;

  const float* A = &g_h[NLAY - 1][0][0];
  for (int kt = 0; kt < HDIM / KS_E; kt += 32) {
    load_A(As, A, HDIM, kc + kt);
    load_B(Bs, w, HDIM, n0, kc + kt);
    __syncthreads();
    mma32(As, Bs, acc, ty, tx);
    __syncthreads();
  }
#pragma unroll
  for (int i = 0; i < 8; i++) {
    int b = ty * 8 + i;
    float* dst = &g_hidp[blockIdx.y][b][n0 + tx * 8];
    *(float4*)(dst)     = make_float4(acc[i][0], acc[i][1], acc[i][2], acc[i][3]);
    *(float4*)(dst + 4) = make_float4(acc[i][4], acc[i][5], acc[i][6], acc[i][7]);
  }
}

__global__ void k_hidred(const float* __restrict__ o2b) {
  int i = blockIdx.x * blockDim.x + threadIdx.x;
  if (i >= BSZ * EDIM) return;
  int b = i >> 10, e = i & (EDIM - 1);
  float s = o2b[e];
#pragma unroll
  for (int c = 0; c < KS_E; c++) s += g_hidp[c][b][e];
  g_hid[b][e] = fmaxf(s, 0.f);
}

// score GEMM + bias + per-block argmax partials; writes scores to d_out[b][t][v]
__global__ __launch_bounds__(128) void k_score(const float* __restrict__ sw,
                                               const float* __restrict__ sb,
                                               float* __restrict__ out, int t) {
  __shared__ float As[32][68];
  __shared__ float Bs[32][132];
  __shared__ float rv[BSZ][16];
  __shared__ int   ri[BSZ][16];
  const int tid = threadIdx.x;
  const int n0 = blockIdx.x * 128;
  const int ty = tid >> 4, tx = tid & 15;
  float acc[8][8];
#pragma unroll
  for (int i = 0; i < 8; i++)
#pragma unroll
    for (int j = 0; j < 8; j++) acc[i][j] = 0.f;

  for (int kt = 0; kt < EDIM; kt += 32) {
    load_A(As, &g_hid[0][0], EDIM, kt);
    load_B(Bs, sw, EDIM, n0, kt);
    __syncthreads();
    mma32(As, Bs, acc, ty, tx);
    __syncthreads();
  }

  float bias[8];
#pragma unroll
  for (int j = 0; j < 8; j++) bias[j] = sb[n0 + tx * 8 + j];

#pragma unroll
  for (int i = 0; i < 8; i++) {
    int b = ty * 8 + i;
    float v[8];
#pragma unroll
    for (int j = 0; j < 8; j++) v[j] = acc[i][j] + bias[j];
    float* dst = out + ((size_t)b * TST + t) * VOCAB + n0 + tx * 8;
    *(float4*)(dst)     = make_float4(v[0], v[1], v[2], v[3]);
    *(float4*)(dst + 4) = make_float4(v[4], v[5], v[6], v[7]);
    float best = v[0];
    int bidx = n0 + tx * 8;
#pragma unroll
    for (int j = 1; j < 8; j++)
      if (v[j] > best) { best = v[j]; bidx = n0 + tx * 8 + j; }
    rv[b][tx] = best; ri[b][tx] = bidx;
  }
  __syncthreads();
  if (tid < BSZ) {
    float best = rv[tid][0]; int bi = ri[tid][0];
#pragma unroll
    for (int x = 1; x < 16; x++) {
      float v = rv[tid][x]; int ix = ri[tid][x];
      if (v > best || (v == best && ix < bi)) { best = v; bi = ix; }
    }
    g_pval[tid][blockIdx.x] = best;
    g_pidx[tid][blockIdx.x] = bi;
  }
}

// final argmax over the 250 block partials; updates tokens, writes samples
__global__ void k_argmax(float* __restrict__ out, int t, int write_samples) {
  int tid = threadIdx.x;          // 256 threads: 4 per batch row
  int b = tid >> 2, l4 = tid & 3;
  float bv = -3.0e38f; int bi = 0x7fffffff;
  for (int p = l4; p < NB_V; p += 4) {
    float v = g_pval[b][p]; int ix = g_pidx[b][p];
    if (v > bv || (v == bv && ix < bi)) { bv = v; bi = ix; }
  }
#pragma unroll
  for (int off = 2; off >= 1; off >>= 1) {
    float ov = __shfl_down_sync(0xffffffffu, bv, off, 4);
    int   oi = __shfl_down_sync(0xffffffffu, bi, off, 4);
    if (ov > bv || (ov == bv && oi < bi)) { bv = ov; bi = oi; }
  }
  if (l4 == 0) {
    g_tok[b] = bi;
    if (write_samples)
      out[(size_t)BSZ * TST * VOCAB + (size_t)b * TST + t] = (float)bi;
  }
}

// ---------------- host orchestration (graph-capturable) ----------------
extern "C" void kernel_launch(void* const* d_in, const int* in_sizes, int n_in,
                              void* d_out, int out_size) {
  const float* emb = (const float*)d_in[0];
  const float* wih = (const float*)d_in[1];
  const float* whh = (const float*)d_in[2];
  const float* bih = (const float*)d_in[3];
  const float* bhh = (const float*)d_in[4];
  const float* o2w = (const float*)d_in[5];
  const float* o2b = (const float*)d_in[6];
  const float* sw  = (const float*)d_in[7];
  const float* sb  = (const float*)d_in[8];
  float* out = (float*)d_out;
  int wsamp = (out_size >= BSZ * TST * VOCAB + BSZ * TST) ? 1 : 0;

  k_init<<<(NLAY * BSZ * HDIM + 255) / 256, 256>>>();

  for (int t = 0; t < TST; t++) {
    for (int l = 0; l < NLAY; l++) {
      k_gates<<<dim3(GDIM / 128, KS_L), 128>>>(emb,
          wih + (size_t)l * GDIM * HDIM, whh + (size_t)l * GDIM * HDIM, l);
      k_act<<<(BSZ * HDIM + 255) / 256, 256>>>(bih + l * GDIM, bhh + l * GDIM, l);
    }
    k_o2emb<<<dim3(EDIM / 128, KS_E), 128>>>(o2w);
    k_hidred<<<(BSZ * EDIM + 255) / 256, 256>>>(o2b);
    k_score<<<NB_V, 128>>>(sw, sb, out, t);
    k_argmax<<<1, 256>>>(out, t, wsamp);
  }
}

// round 3
// speedup vs baseline: 1.0001x; 1.0001x over previous
#include <cuda_runtime.h>

#define VOCAB 32000
#define EDIM  1024
#define HDIM  1024
#define NLAY  2
#define BSZ   64
#define TST   64
#define GDIM  4096          // 4*HDIM
#define KS_L  8             // split-K chunks for LSTM GEMMs (chunk = 128)
#define KS_E  8             // split-K chunks for o2emb GEMM (chunk = 128)
#define NB_V  (VOCAB/128)   // 250 score blocks
#define START_TOK 1

// ---------------- scratch (device globals; no allocation allowed) ----------
__device__ float g_h[NLAY][BSZ][HDIM];
__device__ float g_c[NLAY][BSZ][HDIM];
__device__ float g_gates[KS_L][BSZ][GDIM];
__device__ float g_hidp[KS_E][BSZ][EDIM];
__device__ float g_hid[BSZ][EDIM];
__device__ float g_pval[BSZ][NB_V];
__device__ int   g_pidx[BSZ][NB_V];
__device__ int   g_tok[BSZ];

// ---------------- GEMM tile helpers (BM=64, BN=128, BK=32, 128 thr, 8x8) ---
// As stored transposed [k][b] (stride 68), Bs transposed [k][n] (stride 132)
// so the inner product reads are conflict-free float4 LDS.

__device__ __forceinline__ void load_A(float As[32][68], const float* __restrict__ A,
                                       int lda, int kpos) {
  const int tid = threadIdx.x;
#pragma unroll
  for (int p = 0; p < 4; p++) {
    int idx = p * 128 + tid;
    int r = idx >> 3, c4 = idx & 7;
    float4 v = *(const float4*)(A + (size_t)r * lda + kpos + c4 * 4);
    As[c4 * 4 + 0][r] = v.x; As[c4 * 4 + 1][r] = v.y;
    As[c4 * 4 + 2][r] = v.z; As[c4 * 4 + 3][r] = v.w;
  }
}

__device__ __forceinline__ void load_A_gather(float As[32][68], const float* __restrict__ A,
                                              int lda, int kpos, const int* stok) {
  const int tid = threadIdx.x;
#pragma unroll
  for (int p = 0; p < 4; p++) {
    int idx = p * 128 + tid;
    int r = idx >> 3, c4 = idx & 7;
    int row = stok[r];
    float4 v = *(const float4*)(A + (size_t)row * lda + kpos + c4 * 4);
    As[c4 * 4 + 0][r] = v.x; As[c4 * 4 + 1][r] = v.y;
    As[c4 * 4 + 2][r] = v.z; As[c4 * 4 + 3][r] = v.w;
  }
}

__device__ __forceinline__ void load_B(float Bs[32][132], const float* __restrict__ W,
                                       int ldw, int n0, int kpos) {
  const int tid = threadIdx.x;
#pragma unroll
  for (int p = 0; p < 8; p++) {
    int idx = p * 128 + tid;
    int r = idx >> 3, c4 = idx & 7;
    float4 v = *(const float4*)(W + (size_t)(n0 + r) * ldw + kpos + c4 * 4);
    Bs[c4 * 4 + 0][r] = v.x; Bs[c4 * 4 + 1][r] = v.y;
    Bs[c4 * 4 + 2][r] = v.z; Bs[c4 * 4 + 3][r] = v.w;
  }
}

__device__ __forceinline__ void mma32(const float As[32][68], const float Bs[32][132],
                                      float acc[8][8], int ty, int tx) {
#pragma unroll
  for (int k = 0; k < 32; k++) {
    float a[8], b[8];
    *(float4*)(a)     = *(const float4*)(&As[k][ty * 8]);
    *(float4*)(a + 4) = *(const float4*)(&As[k][ty * 8 + 4]);
    *(float4*)(b)     = *(const float4*)(&Bs[k][tx * 8]);
    *(float4*)(b + 4) = *(const float4*)(&Bs[k][tx * 8 + 4]);
#pragma unroll
    for (int i = 0; i < 8; i++)
#pragma unroll
      for (int j = 0; j < 8; j++)
        acc[i][j] = fmaf(a[i], b[j], acc[i][j]);
  }
}

// ---------------- kernels ----------------

__global__ void k_init() {
  int i = blockIdx.x * blockDim.x + threadIdx.x;
  if (i < NLAY * BSZ * HDIM) {
    (&g_h[0][0][0])[i] = 0.f;
    (&g_c[0][0][0])[i] = 0.f;
  }
  if (i < BSZ) g_tok[i] = START_TOK;
}

// gates partial: g_gates[chunk][b][n] = x@w_ih^T + h@w_hh^T over K-chunk
__global__ __launch_bounds__(128) void k_gates(const float* __restrict__ emb,
                                               const float* __restrict__ wih,
                                               const float* __restrict__ whh,
                                               int layer) {
  __shared__ float As[32][68];
  __shared__ float Bs[32][132];
  __shared__ int stok[BSZ];
  const int tid = threadIdx.x;
  if (layer == 0 && tid < BSZ) stok[tid] = g_tok[tid];
  __syncthreads();

  const int n0 = blockIdx.x * 128;
  const int kc = blockIdx.y * (HDIM / KS_L);
  const int ty = tid >> 4, tx = tid & 15;
  float acc[8][8];
#pragma unroll
  for (int i = 0; i < 8; i++)
#pragma unroll
    for (int j = 0; j < 8; j++) acc[i][j] = 0.f;

  const float* xsrc = (layer == 0) ? emb : &g_h[0][0][0];
  const float* hin  = &g_h[layer][0][0];

  for (int kt = 0; kt < HDIM / KS_L; kt += 32) {
    if (layer == 0) load_A_gather(As, emb, EDIM, kc + kt, stok);
    else            load_A(As, xsrc, HDIM, kc + kt);
    load_B(Bs, wih, HDIM, n0, kc + kt);
    __syncthreads();
    mma32(As, Bs, acc, ty, tx);
    __syncthreads();
  }
  for (int kt = 0; kt < HDIM / KS_L; kt += 32) {
    load_A(As, hin, HDIM, kc + kt);
    load_B(Bs, whh, HDIM, n0, kc + kt);
    __syncthreads();
    mma32(As, Bs, acc, ty, tx);
    __syncthreads();
  }

#pragma unroll
  for (int i = 0; i < 8; i++) {
    int b = ty * 8 + i;
    float* dst = &g_gates[blockIdx.y][b][n0 + tx * 8];
    *(float4*)(dst)     = make_float4(acc[i][0], acc[i][1], acc[i][2], acc[i][3]);
    *(float4*)(dst + 4) = make_float4(acc[i][4], acc[i][5], acc[i][6], acc[i][7]);
  }
}

// reduce split-K partials + biases, apply LSTM cell (gate order i,f,g,o)
__global__ void k_act(const float* __restrict__ bih, const float* __restrict__ bhh,
                      int layer) {
  int i = blockIdx.x * blockDim.x + threadIdx.x;
  if (i >= BSZ * HDIM) return;
  int b = i >> 10, hh = i & (HDIM - 1);
  float gi = bih[hh]            + bhh[hh];
  float gf = bih[HDIM + hh]     + bhh[HDIM + hh];
  float gg = bih[2 * HDIM + hh] + bhh[2 * HDIM + hh];
  float go = bih[3 * HDIM + hh] + bhh[3 * HDIM + hh];
#pragma unroll
  for (int c = 0; c < KS_L; c++) {
    gi += g_gates[c][b][hh];
    gf += g_gates[c][b][HDIM + hh];
    gg += g_gates[c][b][2 * HDIM + hh];
    go += g_gates[c][b][3 * HDIM + hh];
  }
  float si = 1.f / (1.f + expf(-gi));
  float sf = 1.f / (1.f + expf(-gf));
  float so = 1.f / (1.f + expf(-go));
  float tg = tanhf(gg);
  float cn = sf * g_c[layer][b][hh] + si * tg;
  float hn = so * tanhf(cn);
  g_c[layer][b][hh] = cn;
  g_h[layer][b][hh] = hn;
}

// o2emb partial GEMM: g_hidp[chunk][b][e] = h_top @ o2emb_w^T over K-chunk
__global__ __launch_bounds__(128) void k_o2emb(const float* __restrict__ w) {
  __shared__ float As[32][68];
  __shared__ float Bs[32][132];
  const int tid = threadIdx.x;
  const int n0 = blockIdx.x * 128;
  const int kc = blockIdx.y * (HDIM / KS_E);
  const int ty = tid >> 4, tx = tid & 15;
  float acc[8][8];
#pragma unroll
  for (int i = 0; i < 8; i++)
#pragma unroll
    for (int j = 0; j < 8; j++) acc[i][j] = 0.f;

  const float* A = &g_h[NLAY - 1][0][0];
  for (int kt = 0; kt < HDIM / KS_E; kt += 32) {
    load_A(As, A, HDIM, kc + kt);
    load_B(Bs, w, HDIM, n0, kc + kt);
    __syncthreads();
    mma32(As, Bs, acc, ty, tx);
    __syncthreads();
  }
#pragma unroll
  for (int i = 0; i < 8; i++) {
    int b = ty * 8 + i;
    float* dst = &g_hidp[blockIdx.y][b][n0 + tx * 8];
    *(float4*)(dst)     = make_float4(acc[i][0], acc[i][1], acc[i][2], acc[i][3]);
    *(float4*)(dst + 4) = make_float4(acc[i][4], acc[i][5], acc[i][6], acc[i][7]);
  }
}

__global__ void k_hidred(const float* __restrict__ o2b) {
  int i = blockIdx.x * blockDim.x + threadIdx.x;
  if (i >= BSZ * EDIM) return;
  int b = i >> 10, e = i & (EDIM - 1);
  float s = o2b[e];
#pragma unroll
  for (int c = 0; c < KS_E; c++) s += g_hidp[c][b][e];
  g_hid[b][e] = fmaxf(s, 0.f);
}

// score GEMM + bias + per-block argmax partials; writes scores to d_out[b][t][v]
__global__ __launch_bounds__(128) void k_score(const float* __restrict__ sw,
                                               const float* __restrict__ sb,
                                               float* __restrict__ out, int t) {
  __shared__ float As[32][68];
  __shared__ float Bs[32][132];
  __shared__ float rv[BSZ][16];
  __shared__ int   ri[BSZ][16];
  const int tid = threadIdx.x;
  const int n0 = blockIdx.x * 128;
  const int ty = tid >> 4, tx = tid & 15;
  float acc[8][8];
#pragma unroll
  for (int i = 0; i < 8; i++)
#pragma unroll
    for (int j = 0; j < 8; j++) acc[i][j] = 0.f;

  for (int kt = 0; kt < EDIM; kt += 32) {
    load_A(As, &g_hid[0][0], EDIM, kt);
    load_B(Bs, sw, EDIM, n0, kt);
    __syncthreads();
    mma32(As, Bs, acc, ty, tx);
    __syncthreads();
  }

  float bias[8];
#pragma unroll
  for (int j = 0; j < 8; j++) bias[j] = sb[n0 + tx * 8 + j];

#pragma unroll
  for (int i = 0; i < 8; i++) {
    int b = ty * 8 + i;
    float v[8];
#pragma unroll
    for (int j = 0; j < 8; j++) v[j] = acc[i][j] + bias[j];
    float* dst = out + ((size_t)b * TST + t) * VOCAB + n0 + tx * 8;
    *(float4*)(dst)     = make_float4(v[0], v[1], v[2], v[3]);
    *(float4*)(dst + 4) = make_float4(v[4], v[5], v[6], v[7]);
    float best = v[0];
    int bidx = n0 + tx * 8;
#pragma unroll
    for (int j = 1; j < 8; j++)
      if (v[j] > best) { best = v[j]; bidx = n0 + tx * 8 + j; }
    rv[b][tx] = best; ri[b][tx] = bidx;
  }
  __syncthreads();
  if (tid < BSZ) {
    float best = rv[tid][0]; int bi = ri[tid][0];
#pragma unroll
    for (int x = 1; x < 16; x++) {
      float v = rv[tid][x]; int ix = ri[tid][x];
      if (v > best || (v == best && ix < bi)) { best = v; bi = ix; }
    }
    g_pval[tid][blockIdx.x] = best;
    g_pidx[tid][blockIdx.x] = bi;
  }
}

// final argmax over the 250 block partials; updates tokens, writes samples
__global__ void k_argmax(float* __restrict__ out, int t, int write_samples) {
  int tid = threadIdx.x;          // 256 threads: 4 per batch row
  int b = tid >> 2, l4 = tid & 3;
  float bv = -3.0e38f; int bi = 0x7fffffff;
  for (int p = l4; p < NB_V; p += 4) {
    float v = g_pval[b][p]; int ix = g_pidx[b][p];
    if (v > bv || (v == bv && ix < bi)) { bv = v; bi = ix; }
  }
#pragma unroll
  for (int off = 2; off >= 1; off >>= 1) {
    float ov = __shfl_down_sync(0xffffffffu, bv, off, 4);
    int   oi = __shfl_down_sync(0xffffffffu, bi, off, 4);
    if (ov > bv || (ov == bv && oi < bi)) { bv = ov; bi = oi; }
  }
  if (l4 == 0) {
    g_tok[b] = bi;
    if (write_samples)
      out[(size_t)BSZ * TST * VOCAB + (size_t)b * TST + t] = (float)bi;
  }
}

// ---------------- host orchestration (graph-capturable) ----------------
extern "C" void kernel_launch(void* const* d_in, const int* in_sizes, int n_in,
                              void* d_out, int out_size) {
  const float* emb = (const float*)d_in[0];
  const float* wih = (const float*)d_in[1];
  const float* whh = (const float*)d_in[2];
  const float* bih = (const float*)d_in[3];
  const float* bhh = (const float*)d_in[4];
  const float* o2w = (const float*)d_in[5];
  const float* o2b = (const float*)d_in[6];
  const float* sw  = (const float*)d_in[7];
  const float* sb  = (const float*)d_in[8];
  float* out = (float*)d_out;
  int wsamp = (out_size >= BSZ * TST * VOCAB + BSZ * TST) ? 1 : 0;

  k_init<<<(NLAY * BSZ * HDIM + 255) / 256, 256>>>();

  for (int t = 0; t < TST; t++) {
    for (int l = 0; l < NLAY; l++) {
      k_gates<<<dim3(GDIM / 128, KS_L), 128>>>(emb,
          wih + (size_t)l * GDIM * HDIM, whh + (size_t)l * GDIM * HDIM, l);
      k_act<<<(BSZ * HDIM + 255) / 256, 256>>>(bih + l * GDIM, bhh + l * GDIM, l);
    }
    k_o2emb<<<dim3(EDIM / 128, KS_E), 128>>>(o2w);
    k_hidred<<<(BSZ * EDIM + 255) / 256, 256>>>(o2b);
    k_score<<<NB_V, 128>>>(sw, sb, out, t);
    k_argmax<<<1, 256>>>(out, t, wsamp);
  }
}